// round 1
// baseline (speedup 1.0000x reference)
#include <cuda_runtime.h>
#include <cuda_bf16.h>

// Problem constants
constexpr int B = 64;
constexpr int I = 512;
constexpr int T = 512;
constexpr int H = 1024;
constexpr float DECAY = 0.8f;

// GEMM tiling
constexpr int BM = 128;   // t-tile
constexpr int BN = 128;   // h-tile
constexpr int BK = 16;    // i-tile
constexpr int TM = 8;
constexpr int TN = 8;
constexpr int NTHREADS = 256;

// Scratch: proj laid out (T, B, H) so the scan reads coalesced in h.
__device__ float g_proj[(size_t)T * B * H];

// ----------------------------------------------------------------------------
// Phase 1: proj[t,b,h] = sum_i x[b,i,t] * W[i,h]
// A_b = x_b^T is (T,I) "column-major" (t contiguous) -> coalesced tile loads.
// Classic double-buffered (smem ping-pong + register staging) fp32 SGEMM.
// ----------------------------------------------------------------------------
__global__ __launch_bounds__(NTHREADS, 2)
void gemm_kernel(const float* __restrict__ x, const float* __restrict__ W) {
    __shared__ float As[2][BK][BM];
    __shared__ float Bs[2][BK][BN];

    const int tid   = threadIdx.x;
    const int b     = blockIdx.z;
    const int t0    = blockIdx.y * BM;
    const int h0    = blockIdx.x * BN;

    const float* Ab = x + (size_t)b * I * T + t0;  // element (i, t): Ab[i*T + t]
    const float* Bb = W + h0;                       // element (i, n): Bb[i*H + n]

    // Each thread performs 2 float4 loads for A and 2 for B per k-tile.
    const int idx0 = tid;          // 0..255
    const int idx1 = tid + 256;    // 256..511
    const int ka0 = idx0 >> 5, ma0 = (idx0 & 31) << 2;
    const int ka1 = idx1 >> 5, ma1 = (idx1 & 31) << 2;

    // Prologue: load k-tile 0 into smem buffer 0
    float4 aR0 = *(const float4*)(Ab + (size_t)ka0 * T + ma0);
    float4 aR1 = *(const float4*)(Ab + (size_t)ka1 * T + ma1);
    float4 bR0 = *(const float4*)(Bb + (size_t)ka0 * H + ma0);
    float4 bR1 = *(const float4*)(Bb + (size_t)ka1 * H + ma1);
    *(float4*)&As[0][ka0][ma0] = aR0;
    *(float4*)&As[0][ka1][ma1] = aR1;
    *(float4*)&Bs[0][ka0][ma0] = bR0;
    *(float4*)&Bs[0][ka1][ma1] = bR1;
    __syncthreads();

    const int tx  = tid & 15;
    const int ty  = tid >> 4;
    const int tm0 = ty * TM;
    const int tn0 = tx * TN;

    float acc[TM][TN];
#pragma unroll
    for (int i = 0; i < TM; ++i)
#pragma unroll
        for (int j = 0; j < TN; ++j) acc[i][j] = 0.0f;

    constexpr int KT = I / BK;  // 32
    int p = 0;
    for (int kt = 0; kt < KT; ++kt) {
        // Prefetch next k-tile into registers (overlaps with compute)
        if (kt + 1 < KT) {
            const float* An = Ab + (size_t)(kt + 1) * BK * T;
            const float* Bn = Bb + (size_t)(kt + 1) * BK * H;
            aR0 = *(const float4*)(An + (size_t)ka0 * T + ma0);
            aR1 = *(const float4*)(An + (size_t)ka1 * T + ma1);
            bR0 = *(const float4*)(Bn + (size_t)ka0 * H + ma0);
            bR1 = *(const float4*)(Bn + (size_t)ka1 * H + ma1);
        }

        // Compute on buffer p
#pragma unroll
        for (int kk = 0; kk < BK; ++kk) {
            float a[TM], bb[TN];
            *(float4*)&a[0]  = *(const float4*)&As[p][kk][tm0];
            *(float4*)&a[4]  = *(const float4*)&As[p][kk][tm0 + 4];
            *(float4*)&bb[0] = *(const float4*)&Bs[p][kk][tn0];
            *(float4*)&bb[4] = *(const float4*)&Bs[p][kk][tn0 + 4];
#pragma unroll
            for (int i = 0; i < TM; ++i)
#pragma unroll
                for (int j = 0; j < TN; ++j)
                    acc[i][j] += a[i] * bb[j];
        }

        if (kt + 1 < KT) {
            const int q = p ^ 1;
            *(float4*)&As[q][ka0][ma0] = aR0;
            *(float4*)&As[q][ka1][ma1] = aR1;
            *(float4*)&Bs[q][ka0][ma0] = bR0;
            *(float4*)&Bs[q][ka1][ma1] = bR1;
            __syncthreads();
            p = q;
        }
    }

    // Epilogue: proj[t, b, h]
#pragma unroll
    for (int i = 0; i < TM; ++i) {
        const int t = t0 + tm0 + i;
        float* out = g_proj + ((size_t)t * B + b) * H + h0 + tn0;
        *(float4*)(out)     = make_float4(acc[i][0], acc[i][1], acc[i][2], acc[i][3]);
        *(float4*)(out + 4) = make_float4(acc[i][4], acc[i][5], acc[i][6], acc[i][7]);
    }
}

// ----------------------------------------------------------------------------
// Phase 2: sequential recurrence over t. One thread per (b,h) lane.
// 16-deep register double-buffer on the proj stream so each warp keeps ~16
// outstanding DRAM loads (else MLP=1 latency dominates at 14 warps/SM).
// ----------------------------------------------------------------------------
__global__ __launch_bounds__(256)
void scan_kernel(const float* __restrict__ bias, float* __restrict__ out) {
    const int gid = blockIdx.x * blockDim.x + threadIdx.x;   // 0 .. B*H-1
    const int b = gid >> 10;        // H = 1024
    const int h = gid & (H - 1);

    const float bv = __ldg(bias + h);
    const float* p = g_proj + (size_t)b * H + h;
    constexpr int STRIDE = B * H;   // 65536
    constexpr int CH = 16;

    float hc = 0.0f, y = 0.0f;

    float buf[CH];
#pragma unroll
    for (int j = 0; j < CH; ++j) buf[j] = p[(size_t)j * STRIDE];

    for (int tt = 0; tt < T; tt += CH) {
        float nbuf[CH];
        if (tt + CH < T) {
            const float* pn = p + (size_t)(tt + CH) * STRIDE;
#pragma unroll
            for (int j = 0; j < CH; ++j) nbuf[j] = pn[(size_t)j * STRIDE];
        } else {
#pragma unroll
            for (int j = 0; j < CH; ++j) nbuf[j] = 0.0f;
        }
#pragma unroll
        for (int j = 0; j < CH; ++j) {
            const float pr = buf[j];
            // h = relu(p + decay * h * (1 - y))
            hc = fmaxf(pr + DECAY * hc * (1.0f - y), 0.0f);
            // y = (h + b > 1) ? (h + b) : 0
            const float z = hc + bv;
            y = (z > 1.0f) ? z : 0.0f;
        }
#pragma unroll
        for (int j = 0; j < CH; ++j) buf[j] = nbuf[j];
    }

    out[gid] = y;
}

// ----------------------------------------------------------------------------
extern "C" void kernel_launch(void* const* d_in, const int* in_sizes, int n_in,
                              void* d_out, int out_size) {
    const float* x    = (const float*)d_in[0];  // (B, I, T)
    const float* W    = (const float*)d_in[1];  // (I, H)
    const float* bias = (const float*)d_in[2];  // (1, H)
    float* out        = (float*)d_out;          // (B, H)

    dim3 grid(H / BN, T / BM, B);               // 8 x 4 x 64 = 2048 CTAs
    gemm_kernel<<<grid, NTHREADS>>>(x, W);
    scan_kernel<<<(B * H) / 256, 256>>>(bias, out);
}